// round 13
// baseline (speedup 1.0000x reference)
#include <cuda_runtime.h>
#include <cuda_bf16.h>
#include <cstdint>

// Problem constants
#define BB 4
#define CC_FEAT 96
#define HH 192
#define WW 192
#define HW (HH*WW)
#define MD 3
#define ND 49

// ---------------- scratch (device globals; no allocation allowed) ----------------
__device__ float g_flow [BB*2*HW];
__device__ float g_feat2[BB*CC_FEAT*HW];
__device__ float g_corr [BB*ND*HW];
__device__ float g_x1   [BB*128*HW];
__device__ float g_x2   [BB*64 *HW];
__device__ float g_x3   [BB*32 *HW];
// duplicated (w,w) weight pairs, slab layout per (oc_block, chunk)
__device__ unsigned long long g_wdup[160000];
#define WD_OFF1 0
#define WD_OFF2 56448      // 16*7*7*9*8
#define WD_OFF3 130176     // + 8*32*4*9*8
#define WD_OFF4 148608     // + 4*16*4*9*8
// conv4: + 1*8*4*25*2 = 1600 -> end 150208

// ---------------- f32x2 helpers ----------------
__device__ __forceinline__ unsigned long long pk2(float lo, float hi) {
    unsigned long long r;
    asm("mov.b64 %0, {%1, %2};" : "=l"(r) : "f"(lo), "f"(hi));
    return r;
}
__device__ __forceinline__ void upk2(unsigned long long v, float& lo, float& hi) {
    asm("mov.b64 {%0, %1}, %2;" : "=f"(lo), "=f"(hi) : "l"(v));
}
__device__ __forceinline__ void fma2(unsigned long long& d, unsigned long long a, unsigned long long b) {
    asm("fma.rn.f32x2 %0, %1, %2, %0;" : "+l"(d) : "l"(a), "l"(b));
}

// ---------------- cp.async helpers ----------------
__device__ __forceinline__ void cp4(unsigned int dst_smem, const void* src, unsigned int src_sz) {
    asm volatile("cp.async.ca.shared.global [%0], [%1], 4, %2;"
                 :: "r"(dst_smem), "l"(src), "r"(src_sz));
}
__device__ __forceinline__ void cp16(unsigned int dst_smem, const void* src) {
    asm volatile("cp.async.cg.shared.global [%0], [%1], 16;"
                 :: "r"(dst_smem), "l"(src));
}
__device__ __forceinline__ void cp_commit() {
    asm volatile("cp.async.commit_group;");
}
template<int N>
__device__ __forceinline__ void cp_wait() {
    asm volatile("cp.async.wait_group %0;" :: "n"(N));
}

// ---------------- 0) weight duplication prep ----------------
__global__ void __launch_bounds__(256) dupw_k(const float* __restrict__ w,
                                              unsigned long long* __restrict__ dst,
                                              int total, int CI, int KS2,
                                              int CCH, int OC_N, int NC)
{
    int i = blockIdx.x * 256 + threadIdx.x;
    if (i >= total) return;
    int oc = i % OC_N; int t = i / OC_N;
    int k  = t % KS2;  t /= KS2;
    int ci = t % CCH;  t /= CCH;
    int c  = t % NC;   int pb = t / NC;
    float wv = w[((pb*OC_N + oc)*CI + c*CCH + ci)*KS2 + k];
    unsigned int u = __float_as_uint(wv);
    dst[i] = (unsigned long long)u | ((unsigned long long)u << 32);
}

// ---------------- 1) upflow ----------------
__global__ void __launch_bounds__(256) upflow_k(const float* __restrict__ fl,
                                                const float* __restrict__ w)
{
    int idx = blockIdx.x * 256 + threadIdx.x;
    if (idx >= BB*2*HW) return;
    int x = idx % WW;
    int y = (idx / WW) % HH;
    int g = (idx / HW) % 2;
    int b = idx / (2*HW);
    float acc = 0.f;
#pragma unroll
    for (int ky = 0; ky < 4; ky++) {
        int t = y + ky - 2;
        if (t & 1) continue;
        int iy = t >> 1;
        if (iy < 0 || iy >= 96) continue;
#pragma unroll
        for (int kx = 0; kx < 4; kx++) {
            int s = x + kx - 2;
            if (s & 1) continue;
            int ix = s >> 1;
            if (ix < 0 || ix >= 96) continue;
            acc += w[g*16 + (3-ky)*4 + (3-kx)] * fl[((b*2 + g)*96 + iy)*96 + ix];
        }
    }
    g_flow[idx] = acc;
}

// ---------------- 2) backwarp ----------------
__global__ void __launch_bounds__(256) backwarp_k(const float* __restrict__ feat)
{
    int idx = blockIdx.x * 256 + threadIdx.x;
    if (idx >= BB*HW) return;
    int x = idx % WW;
    int y = (idx / WW) % HH;
    int b = idx / HW;

    float fx = 2.5f * g_flow[(b*2 + 0)*HW + y*WW + x];
    float fy = 2.5f * g_flow[(b*2 + 1)*HW + y*WW + x];
    float gx = (float)x + fx;
    float gy = (float)y + fy;
    float x0f = floorf(gx), y0f = floorf(gy);
    float wx = gx - x0f, wy = gy - y0f;
    int x0 = (int)x0f, y0 = (int)y0f;
    int x1 = x0 + 1,  y1 = y0 + 1;

    float v00 = (x0 >= 0 && x0 < WW && y0 >= 0 && y0 < HH) ? 1.f : 0.f;
    float v01 = (x1 >= 0 && x1 < WW && y0 >= 0 && y0 < HH) ? 1.f : 0.f;
    float v10 = (x0 >= 0 && x0 < WW && y1 >= 0 && y1 < HH) ? 1.f : 0.f;
    float v11 = (x1 >= 0 && x1 < WW && y1 >= 0 && y1 < HH) ? 1.f : 0.f;

    int cx0 = min(max(x0, 0), WW-1), cx1 = min(max(x1, 0), WW-1);
    int cy0 = min(max(y0, 0), HH-1), cy1 = min(max(y1, 0), HH-1);

    float w00 = (1.f-wy)*(1.f-wx) * v00;
    float w01 = (1.f-wy)*wx       * v01;
    float w10 = wy*(1.f-wx)       * v10;
    float w11 = wy*wx             * v11;

    int o00 = cy0*WW + cx0, o01 = cy0*WW + cx1;
    int o10 = cy1*WW + cx0, o11 = cy1*WW + cx1;

    const float* fb = feat + (size_t)b*CC_FEAT*HW;
    float* ob = g_feat2 + (size_t)b*CC_FEAT*HW + y*WW + x;
#pragma unroll 4
    for (int c = 0; c < CC_FEAT; c++) {
        const float* p = fb + c*HW;
        ob[c*HW] = w00*p[o00] + w01*p[o01] + w10*p[o10] + w11*p[o11];
    }
}

// ---------------- 3) correlation + leaky ----------------
__global__ void __launch_bounds__(256) corr_k(const float* __restrict__ f1)
{
    __shared__ float s2[8][14][38];
    const int tx = threadIdx.x, ty = threadIdx.y;
    const int tid = ty*32 + tx;
    const int x0 = blockIdx.x * 32, y0 = blockIdx.y * 8;
    const int b = blockIdx.z;
    const int x = x0 + tx, y = y0 + ty;

    float acc[ND];
#pragma unroll
    for (int d = 0; d < ND; d++) acc[d] = 0.f;

    for (int cc0 = 0; cc0 < CC_FEAT; cc0 += 8) {
        for (int i = tid; i < 8*14*38; i += 256) {
            int ci  = i / (14*38);
            int rem = i - ci*(14*38);
            int r   = rem / 38;
            int cl  = rem - r*38;
            int gy = y0 + r - MD, gx = x0 + cl - MD;
            float v = 0.f;
            if (gy >= 0 && gy < HH && gx >= 0 && gx < WW)
                v = g_feat2[((b*CC_FEAT + cc0 + ci)*HH + gy)*WW + gx];
            s2[ci][r][cl] = v;
        }
        __syncthreads();

#pragma unroll 1
        for (int ci = 0; ci < 8; ci++) {
            float fv = f1[((b*CC_FEAT + cc0 + ci)*HH + y)*WW + x];
#pragma unroll
            for (int dy = 0; dy < 7; dy++)
#pragma unroll
                for (int dx = 0; dx < 7; dx++)
                    acc[dy*7 + dx] += fv * s2[ci][ty + dy][tx + dx];
        }
        __syncthreads();
    }

#pragma unroll
    for (int d = 0; d < ND; d++) {
        float v = acc[d] * (1.f / 96.f);
        v = (v >= 0.f) ? v : 0.1f * v;
        g_corr[((b*ND + d)*HH + y)*WW + x] = v;
    }
}

// ---------------- 4) direct conv: row-pair FFMA2, pre-duplicated weights ----------
// block (32,TY); tile 32x32. NPACKS = 32/(2*TY) row-pair packs per thread:
// pack p = rows (ty + p*2*TY, ty + p*2*TY + TY).
// TY=8  -> 256 thr, 2 packs (R9-proven shape, conv2/3/4)
// TY=16 -> 512 thr, 1 pack  (conv1: fewer regs, 32 warps/SM @72.8KB smem)
// Per k-step per thread: NPACKS*2 LDS.32 + OC_N/2 LDS.128(bcast) + NPACKS*OC_N FFMA2.
template<int CI, int CO, int KS, int CCH, int OC_N, int TY, bool LEAKY, bool ADD_FLOW>
__global__ void __launch_bounds__(32*TY, (TY==16) ? 2 : 4)
conv2d_k(const float* __restrict__ in,
         const unsigned long long* __restrict__ wdup,
         const float* __restrict__ bias,
         float* __restrict__ out)
{
    constexpr int THREADS = 32*TY;
    constexpr int NPACKS = 32/(2*TY);
    constexpr int PADK = KS / 2;
    constexpr int SH = 32 + 2*PADK;
    constexpr int SW = 32 + 2*PADK;
    constexpr int PLANE = SH*SW;
    constexpr int NC = CI / CCH;
    constexpr int IN_ELEMS = CCH*PLANE;
    constexpr int WU64 = CCH*KS*KS*OC_N;
    constexpr int NPOS = (PLANE + THREADS - 1) / THREADS;

    extern __shared__ float dynsmem[];
    float* s_in = dynsmem;                                           // [2][IN_ELEMS]
    unsigned long long* s_w =
        reinterpret_cast<unsigned long long*>(dynsmem + 2*IN_ELEMS); // [2][WU64]

    const int tx = threadIdx.x, ty = threadIdx.y;
    const int tid = ty*32 + tx;
    const int x0 = blockIdx.x * 32, y0 = blockIdx.y * 32;
    constexpr int PER_B = CO / OC_N;
    const int b  = blockIdx.z / PER_B;
    const int pb = blockIdx.z % PER_B;
    const int ocb = pb * OC_N;

    int gofs[NPOS];
    unsigned int oksz[NPOS];
#pragma unroll
    for (int n = 0; n < NPOS; n++) {
        int i = tid + n*THREADS;
        int r  = i / SW;
        int cl = i - r*SW;
        int gy = y0 + r - PADK, gx = x0 + cl - PADK;
        bool ok = (i < PLANE) && (gy >= 0) && (gy < HH) && (gx >= 0) && (gx < WW);
        gofs[n] = ok ? gy*WW + gx : 0;
        oksz[n] = ok ? 4u : 0u;
    }

    const unsigned long long* wslab = wdup + (size_t)pb*NC*WU64;

    unsigned long long acc[NPACKS][OC_N];
#pragma unroll
    for (int p = 0; p < NPACKS; p++)
#pragma unroll
        for (int i = 0; i < OC_N; i++) acc[p][i] = 0ull;

    auto issue = [&](int c, int buf) {
        const float* inb = in + (size_t)(b*CI + c*CCH)*HW;
        unsigned int dbase = (unsigned int)__cvta_generic_to_shared(s_in + buf*IN_ELEMS);
#pragma unroll
        for (int ci = 0; ci < CCH; ci++) {
#pragma unroll
            for (int n = 0; n < NPOS; n++) {
                int i = tid + n*THREADS;
                if (NPOS*THREADS != PLANE && i >= PLANE) break;
                cp4(dbase + (unsigned int)(ci*PLANE + i)*4u,
                    inb + ci*HW + gofs[n], oksz[n]);
            }
        }
        unsigned int wbase = (unsigned int)__cvta_generic_to_shared(s_w + buf*WU64);
        const unsigned long long* wsrc = wslab + (size_t)c*WU64;
#pragma unroll 1
        for (int i = tid; i < WU64/2; i += THREADS)
            cp16(wbase + (unsigned int)i*16u, wsrc + 2*i);
        cp_commit();
    };

    auto compute = [&](int buf) {
        const float* din = s_in + buf*IN_ELEMS;
        const unsigned long long* dw = s_w + buf*WU64;
#pragma unroll 1
        for (int ci = 0; ci < CCH; ci++) {
            const float* tb = din + ci*PLANE + ty*SW + tx;
#pragma unroll
            for (int ky = 0; ky < KS; ky++) {
#pragma unroll
                for (int kx = 0; kx < KS; kx++) {
                    unsigned long long P[NPACKS];
#pragma unroll
                    for (int p = 0; p < NPACKS; p++) {
                        float a0 = tb[(ky + p*2*TY     )*SW + kx];
                        float a1 = tb[(ky + p*2*TY + TY)*SW + kx];
                        P[p] = pk2(a0, a1);
                    }
                    const ulonglong2* wr = reinterpret_cast<const ulonglong2*>(
                        dw + (ci*KS*KS + ky*KS + kx)*OC_N);
#pragma unroll
                    for (int j = 0; j < OC_N/2; j++) {
                        ulonglong2 w2 = wr[j];
#pragma unroll
                        for (int p = 0; p < NPACKS; p++) {
                            fma2(acc[p][2*j  ], P[p], w2.x);
                            fma2(acc[p][2*j+1], P[p], w2.y);
                        }
                    }
                }
            }
        }
    };

    issue(0, 0);
#pragma unroll 1
    for (int c = 0; c < NC; c++) {
        if (c + 1 < NC) { issue(c + 1, (c + 1) & 1); cp_wait<1>(); }
        else            { cp_wait<0>(); }
        __syncthreads();
        compute(c & 1);
        __syncthreads();
    }

    const int x = x0 + tx;
#pragma unroll
    for (int oc = 0; oc < OC_N; oc++) {
        float bv = bias[ocb + oc];
#pragma unroll
        for (int p = 0; p < NPACKS; p++) {
            float r0, r1;
            upk2(acc[p][oc], r0, r1);
            int ya = y0 + ty + p*2*TY;
            int yb = ya + TY;
            r0 += bv; r1 += bv;
            if (LEAKY) {
                r0 = (r0 >= 0.f) ? r0 : 0.1f * r0;
                r1 = (r1 >= 0.f) ? r1 : 0.1f * r1;
            }
            if (ADD_FLOW) {
                r0 += g_flow[((b*2 + ocb + oc)*HH + ya)*WW + x];
                r1 += g_flow[((b*2 + ocb + oc)*HH + yb)*WW + x];
            }
            out[((b*CO + ocb + oc)*HH + ya)*WW + x] = r0;
            out[((b*CO + ocb + oc)*HH + yb)*WW + x] = r1;
        }
    }
}

// ---------------- launch ----------------
template<int CCH, int KS, int OC_N>
constexpr int conv_smem() {
    constexpr int SH = 32 + 2*(KS/2);
    return 2*CCH*SH*SH*4 + 2*CCH*KS*KS*OC_N*8;
}

extern "C" void kernel_launch(void* const* d_in, const int* in_sizes, int n_in,
                              void* d_out, int out_size)
{
    const float* f1      = (const float*)d_in[2];
    const float* f2      = (const float*)d_in[3];
    const float* flow_in = (const float*)d_in[4];
    const float* w_up    = (const float*)d_in[5];
    const float* w1 = (const float*)d_in[6];
    const float* b1 = (const float*)d_in[7];
    const float* w2 = (const float*)d_in[8];
    const float* b2 = (const float*)d_in[9];
    const float* w3 = (const float*)d_in[10];
    const float* b3 = (const float*)d_in[11];
    const float* w4 = (const float*)d_in[12];
    const float* b4 = (const float*)d_in[13];
    float* out = (float*)d_out;

    void *pcorr, *px1, *px2, *px3, *pwd;
    cudaGetSymbolAddress(&pcorr, g_corr);
    cudaGetSymbolAddress(&px1,   g_x1);
    cudaGetSymbolAddress(&px2,   g_x2);
    cudaGetSymbolAddress(&px3,   g_x3);
    cudaGetSymbolAddress(&pwd,   g_wdup);
    unsigned long long* wd = (unsigned long long*)pwd;

    constexpr int SM1 = conv_smem<7, 3, 8>();   // 72800 B
    constexpr int SM2 = conv_smem<4, 3, 8>();   // 41600 B
    constexpr int SM3 = conv_smem<4, 3, 8>();
    constexpr int SM4 = conv_smem<4, 5, 2>();   // 44672 B

    static bool attr_done = false;
    if (!attr_done) {
        cudaFuncSetAttribute(conv2d_k<49, 128, 3, 7, 8, 16, true,  false>,
                             cudaFuncAttributeMaxDynamicSharedMemorySize, SM1);
        cudaFuncSetAttribute(conv2d_k<128, 64, 3, 4, 8, 8, true,  false>,
                             cudaFuncAttributeMaxDynamicSharedMemorySize, SM2);
        cudaFuncSetAttribute(conv2d_k<64,  32, 3, 4, 8, 8, true,  false>,
                             cudaFuncAttributeMaxDynamicSharedMemorySize, SM3);
        cudaFuncSetAttribute(conv2d_k<32,   2, 5, 4, 2, 8, false, true >,
                             cudaFuncAttributeMaxDynamicSharedMemorySize, SM4);
        attr_done = true;
    }

    // 0) weight duplication (slabs per oc-block x chunk)
    dupw_k<<<(56448 + 255)/256, 256>>>(w1, wd + WD_OFF1, 56448, 49, 9, 7, 8, 7);
    dupw_k<<<(73728 + 255)/256, 256>>>(w2, wd + WD_OFF2, 73728, 128, 9, 4, 8, 32);
    dupw_k<<<(18432 + 255)/256, 256>>>(w3, wd + WD_OFF3, 18432, 64, 9, 4, 8, 16);
    dupw_k<<<(1600  + 255)/256, 256>>>(w4, wd + WD_OFF4, 1600, 32, 25, 4, 2, 8);

    // 1) upflow
    upflow_k<<<(BB*2*HW + 255)/256, 256>>>(flow_in, w_up);
    // 2) backwarp
    backwarp_k<<<(BB*HW + 255)/256, 256>>>(f2);
    // 3) correlation + leaky
    corr_k<<<dim3(WW/32, HH/8, BB), dim3(32, 8)>>>(f1);
    // 4) conv chain (conv1: 512-thread blocks for occupancy; others R9 shape)
    conv2d_k<49, 128, 3, 7, 8, 16, true,  false><<<dim3(6, 6, BB*16), dim3(32, 16), SM1>>>(
        (const float*)pcorr, wd + WD_OFF1, b1, (float*)px1);
    conv2d_k<128, 64, 3, 4, 8, 8, true,  false><<<dim3(6, 6, BB*8),  dim3(32, 8), SM2>>>(
        (const float*)px1,   wd + WD_OFF2, b2, (float*)px2);
    conv2d_k<64,  32, 3, 4, 8, 8, true,  false><<<dim3(6, 6, BB*4),  dim3(32, 8), SM3>>>(
        (const float*)px2,   wd + WD_OFF3, b3, (float*)px3);
    conv2d_k<32,   2, 5, 4, 2, 8, false, true ><<<dim3(6, 6, BB*1),  dim3(32, 8), SM4>>>(
        (const float*)px3,   wd + WD_OFF4, b4, out);
}

// round 14
// speedup vs baseline: 1.0033x; 1.0033x over previous
#include <cuda_runtime.h>
#include <cuda_bf16.h>
#include <cstdint>

// Problem constants
#define BB 4
#define CC_FEAT 96
#define HH 192
#define WW 192
#define HW (HH*WW)
#define MD 3
#define ND 49

// ---------------- scratch (device globals; no allocation allowed) ----------------
__device__ float g_flow [BB*2*HW];
__device__ float g_feat2[BB*CC_FEAT*HW];
__device__ float g_corr [BB*ND*HW];
__device__ float g_x1   [BB*128*HW];
__device__ float g_x2   [BB*64 *HW];
__device__ float g_x3   [BB*32 *HW];
// duplicated (w,w) weight pairs, slab layout per (oc_block, chunk)
__device__ unsigned long long g_wdup[160000];
#define WD_OFF1 0
#define WD_OFF2 56448      // 16*7*7*9*8
#define WD_OFF3 130176     // + 8*32*4*9*8
#define WD_OFF4 148608     // + 4*16*4*9*8
// conv4: + 1*8*4*25*2 = 1600 -> end 150208

// ---------------- f32x2 helpers ----------------
__device__ __forceinline__ unsigned long long pk2(float lo, float hi) {
    unsigned long long r;
    asm("mov.b64 %0, {%1, %2};" : "=l"(r) : "f"(lo), "f"(hi));
    return r;
}
__device__ __forceinline__ void upk2(unsigned long long v, float& lo, float& hi) {
    asm("mov.b64 {%0, %1}, %2;" : "=f"(lo), "=f"(hi) : "l"(v));
}
__device__ __forceinline__ void fma2(unsigned long long& d, unsigned long long a, unsigned long long b) {
    asm("fma.rn.f32x2 %0, %1, %2, %0;" : "+l"(d) : "l"(a), "l"(b));
}

// ---------------- cp.async helpers ----------------
__device__ __forceinline__ void cp4(unsigned int dst_smem, const void* src, unsigned int src_sz) {
    asm volatile("cp.async.ca.shared.global [%0], [%1], 4, %2;"
                 :: "r"(dst_smem), "l"(src), "r"(src_sz));
}
__device__ __forceinline__ void cp16(unsigned int dst_smem, const void* src) {
    asm volatile("cp.async.cg.shared.global [%0], [%1], 16;"
                 :: "r"(dst_smem), "l"(src));
}
__device__ __forceinline__ void cp_commit() {
    asm volatile("cp.async.commit_group;");
}
template<int N>
__device__ __forceinline__ void cp_wait() {
    asm volatile("cp.async.wait_group %0;" :: "n"(N));
}

// ---------------- 0) weight duplication prep ----------------
__global__ void __launch_bounds__(256) dupw_k(const float* __restrict__ w,
                                              unsigned long long* __restrict__ dst,
                                              int total, int CI, int KS2,
                                              int CCH, int OC_N, int NC)
{
    int i = blockIdx.x * 256 + threadIdx.x;
    if (i >= total) return;
    int oc = i % OC_N; int t = i / OC_N;
    int k  = t % KS2;  t /= KS2;
    int ci = t % CCH;  t /= CCH;
    int c  = t % NC;   int pb = t / NC;
    float wv = w[((pb*OC_N + oc)*CI + c*CCH + ci)*KS2 + k];
    unsigned int u = __float_as_uint(wv);
    dst[i] = (unsigned long long)u | ((unsigned long long)u << 32);
}

// ---------------- 1) upflow ----------------
__global__ void __launch_bounds__(256) upflow_k(const float* __restrict__ fl,
                                                const float* __restrict__ w)
{
    int idx = blockIdx.x * 256 + threadIdx.x;
    if (idx >= BB*2*HW) return;
    int x = idx % WW;
    int y = (idx / WW) % HH;
    int g = (idx / HW) % 2;
    int b = idx / (2*HW);
    float acc = 0.f;
#pragma unroll
    for (int ky = 0; ky < 4; ky++) {
        int t = y + ky - 2;
        if (t & 1) continue;
        int iy = t >> 1;
        if (iy < 0 || iy >= 96) continue;
#pragma unroll
        for (int kx = 0; kx < 4; kx++) {
            int s = x + kx - 2;
            if (s & 1) continue;
            int ix = s >> 1;
            if (ix < 0 || ix >= 96) continue;
            acc += w[g*16 + (3-ky)*4 + (3-kx)] * fl[((b*2 + g)*96 + iy)*96 + ix];
        }
    }
    g_flow[idx] = acc;
}

// ---------------- 2) backwarp ----------------
__global__ void __launch_bounds__(256) backwarp_k(const float* __restrict__ feat)
{
    int idx = blockIdx.x * 256 + threadIdx.x;
    if (idx >= BB*HW) return;
    int x = idx % WW;
    int y = (idx / WW) % HH;
    int b = idx / HW;

    float fx = 2.5f * g_flow[(b*2 + 0)*HW + y*WW + x];
    float fy = 2.5f * g_flow[(b*2 + 1)*HW + y*WW + x];
    float gx = (float)x + fx;
    float gy = (float)y + fy;
    float x0f = floorf(gx), y0f = floorf(gy);
    float wx = gx - x0f, wy = gy - y0f;
    int x0 = (int)x0f, y0 = (int)y0f;
    int x1 = x0 + 1,  y1 = y0 + 1;

    float v00 = (x0 >= 0 && x0 < WW && y0 >= 0 && y0 < HH) ? 1.f : 0.f;
    float v01 = (x1 >= 0 && x1 < WW && y0 >= 0 && y0 < HH) ? 1.f : 0.f;
    float v10 = (x0 >= 0 && x0 < WW && y1 >= 0 && y1 < HH) ? 1.f : 0.f;
    float v11 = (x1 >= 0 && x1 < WW && y1 >= 0 && y1 < HH) ? 1.f : 0.f;

    int cx0 = min(max(x0, 0), WW-1), cx1 = min(max(x1, 0), WW-1);
    int cy0 = min(max(y0, 0), HH-1), cy1 = min(max(y1, 0), HH-1);

    float w00 = (1.f-wy)*(1.f-wx) * v00;
    float w01 = (1.f-wy)*wx       * v01;
    float w10 = wy*(1.f-wx)       * v10;
    float w11 = wy*wx             * v11;

    int o00 = cy0*WW + cx0, o01 = cy0*WW + cx1;
    int o10 = cy1*WW + cx0, o11 = cy1*WW + cx1;

    const float* fb = feat + (size_t)b*CC_FEAT*HW;
    float* ob = g_feat2 + (size_t)b*CC_FEAT*HW + y*WW + x;
#pragma unroll 4
    for (int c = 0; c < CC_FEAT; c++) {
        const float* p = fb + c*HW;
        ob[c*HW] = w00*p[o00] + w01*p[o01] + w10*p[o10] + w11*p[o11];
    }
}

// ---------------- 3) correlation + leaky ----------------
__global__ void __launch_bounds__(256) corr_k(const float* __restrict__ f1)
{
    __shared__ float s2[8][14][38];
    const int tx = threadIdx.x, ty = threadIdx.y;
    const int tid = ty*32 + tx;
    const int x0 = blockIdx.x * 32, y0 = blockIdx.y * 8;
    const int b = blockIdx.z;
    const int x = x0 + tx, y = y0 + ty;

    float acc[ND];
#pragma unroll
    for (int d = 0; d < ND; d++) acc[d] = 0.f;

    for (int cc0 = 0; cc0 < CC_FEAT; cc0 += 8) {
        for (int i = tid; i < 8*14*38; i += 256) {
            int ci  = i / (14*38);
            int rem = i - ci*(14*38);
            int r   = rem / 38;
            int cl  = rem - r*38;
            int gy = y0 + r - MD, gx = x0 + cl - MD;
            float v = 0.f;
            if (gy >= 0 && gy < HH && gx >= 0 && gx < WW)
                v = g_feat2[((b*CC_FEAT + cc0 + ci)*HH + gy)*WW + gx];
            s2[ci][r][cl] = v;
        }
        __syncthreads();

#pragma unroll 1
        for (int ci = 0; ci < 8; ci++) {
            float fv = f1[((b*CC_FEAT + cc0 + ci)*HH + y)*WW + x];
#pragma unroll
            for (int dy = 0; dy < 7; dy++)
#pragma unroll
                for (int dx = 0; dx < 7; dx++)
                    acc[dy*7 + dx] += fv * s2[ci][ty + dy][tx + dx];
        }
        __syncthreads();
    }

#pragma unroll
    for (int d = 0; d < ND; d++) {
        float v = acc[d] * (1.f / 96.f);
        v = (v >= 0.f) ? v : 0.1f * v;
        g_corr[((b*ND + d)*HH + y)*WW + x] = v;
    }
}

// ---------------- 4) direct conv: row-pair FFMA2, pre-duplicated weights ----------
// block (32,TY); tile 32x32. NPACKS = 32/(2*TY) row-pair packs per thread:
// pack p = rows (ty + p*2*TY, ty + p*2*TY + TY).
// TY=8  -> 256 thr, 2 packs (R9-proven shape, conv2/3/4)
// TY=16 -> 512 thr, 1 pack  (conv1: fewer regs, 32 warps/SM @72.8KB smem)
// Per k-step per thread: NPACKS*2 LDS.32 + OC_N/2 LDS.128(bcast) + NPACKS*OC_N FFMA2.
template<int CI, int CO, int KS, int CCH, int OC_N, int TY, bool LEAKY, bool ADD_FLOW>
__global__ void __launch_bounds__(32*TY, (TY==16) ? 2 : 4)
conv2d_k(const float* __restrict__ in,
         const unsigned long long* __restrict__ wdup,
         const float* __restrict__ bias,
         float* __restrict__ out)
{
    constexpr int THREADS = 32*TY;
    constexpr int NPACKS = 32/(2*TY);
    constexpr int PADK = KS / 2;
    constexpr int SH = 32 + 2*PADK;
    constexpr int SW = 32 + 2*PADK;
    constexpr int PLANE = SH*SW;
    constexpr int NC = CI / CCH;
    constexpr int IN_ELEMS = CCH*PLANE;
    constexpr int WU64 = CCH*KS*KS*OC_N;
    constexpr int NPOS = (PLANE + THREADS - 1) / THREADS;

    extern __shared__ float dynsmem[];
    float* s_in = dynsmem;                                           // [2][IN_ELEMS]
    unsigned long long* s_w =
        reinterpret_cast<unsigned long long*>(dynsmem + 2*IN_ELEMS); // [2][WU64]

    const int tx = threadIdx.x, ty = threadIdx.y;
    const int tid = ty*32 + tx;
    const int x0 = blockIdx.x * 32, y0 = blockIdx.y * 32;
    constexpr int PER_B = CO / OC_N;
    const int b  = blockIdx.z / PER_B;
    const int pb = blockIdx.z % PER_B;
    const int ocb = pb * OC_N;

    int gofs[NPOS];
    unsigned int oksz[NPOS];
#pragma unroll
    for (int n = 0; n < NPOS; n++) {
        int i = tid + n*THREADS;
        int r  = i / SW;
        int cl = i - r*SW;
        int gy = y0 + r - PADK, gx = x0 + cl - PADK;
        bool ok = (i < PLANE) && (gy >= 0) && (gy < HH) && (gx >= 0) && (gx < WW);
        gofs[n] = ok ? gy*WW + gx : 0;
        oksz[n] = ok ? 4u : 0u;
    }

    const unsigned long long* wslab = wdup + (size_t)pb*NC*WU64;

    unsigned long long acc[NPACKS][OC_N];
#pragma unroll
    for (int p = 0; p < NPACKS; p++)
#pragma unroll
        for (int i = 0; i < OC_N; i++) acc[p][i] = 0ull;

    auto issue = [&](int c, int buf) {
        const float* inb = in + (size_t)(b*CI + c*CCH)*HW;
        unsigned int dbase = (unsigned int)__cvta_generic_to_shared(s_in + buf*IN_ELEMS);
#pragma unroll
        for (int ci = 0; ci < CCH; ci++) {
#pragma unroll
            for (int n = 0; n < NPOS; n++) {
                int i = tid + n*THREADS;
                if (NPOS*THREADS != PLANE && i >= PLANE) break;
                cp4(dbase + (unsigned int)(ci*PLANE + i)*4u,
                    inb + ci*HW + gofs[n], oksz[n]);
            }
        }
        unsigned int wbase = (unsigned int)__cvta_generic_to_shared(s_w + buf*WU64);
        const unsigned long long* wsrc = wslab + (size_t)c*WU64;
#pragma unroll 1
        for (int i = tid; i < WU64/2; i += THREADS)
            cp16(wbase + (unsigned int)i*16u, wsrc + 2*i);
        cp_commit();
    };

    auto compute = [&](int buf) {
        const float* din = s_in + buf*IN_ELEMS;
        const unsigned long long* dw = s_w + buf*WU64;
#pragma unroll 1
        for (int ci = 0; ci < CCH; ci++) {
            const float* tb = din + ci*PLANE + ty*SW + tx;
#pragma unroll
            for (int ky = 0; ky < KS; ky++) {
#pragma unroll
                for (int kx = 0; kx < KS; kx++) {
                    unsigned long long P[NPACKS];
#pragma unroll
                    for (int p = 0; p < NPACKS; p++) {
                        float a0 = tb[(ky + p*2*TY     )*SW + kx];
                        float a1 = tb[(ky + p*2*TY + TY)*SW + kx];
                        P[p] = pk2(a0, a1);
                    }
                    const ulonglong2* wr = reinterpret_cast<const ulonglong2*>(
                        dw + (ci*KS*KS + ky*KS + kx)*OC_N);
#pragma unroll
                    for (int j = 0; j < OC_N/2; j++) {
                        ulonglong2 w2 = wr[j];
#pragma unroll
                        for (int p = 0; p < NPACKS; p++) {
                            fma2(acc[p][2*j  ], P[p], w2.x);
                            fma2(acc[p][2*j+1], P[p], w2.y);
                        }
                    }
                }
            }
        }
    };

    issue(0, 0);
#pragma unroll 1
    for (int c = 0; c < NC; c++) {
        if (c + 1 < NC) { issue(c + 1, (c + 1) & 1); cp_wait<1>(); }
        else            { cp_wait<0>(); }
        __syncthreads();
        compute(c & 1);
        __syncthreads();
    }

    const int x = x0 + tx;
#pragma unroll
    for (int oc = 0; oc < OC_N; oc++) {
        float bv = bias[ocb + oc];
#pragma unroll
        for (int p = 0; p < NPACKS; p++) {
            float r0, r1;
            upk2(acc[p][oc], r0, r1);
            int ya = y0 + ty + p*2*TY;
            int yb = ya + TY;
            r0 += bv; r1 += bv;
            if (LEAKY) {
                r0 = (r0 >= 0.f) ? r0 : 0.1f * r0;
                r1 = (r1 >= 0.f) ? r1 : 0.1f * r1;
            }
            if (ADD_FLOW) {
                r0 += g_flow[((b*2 + ocb + oc)*HH + ya)*WW + x];
                r1 += g_flow[((b*2 + ocb + oc)*HH + yb)*WW + x];
            }
            out[((b*CO + ocb + oc)*HH + ya)*WW + x] = r0;
            out[((b*CO + ocb + oc)*HH + yb)*WW + x] = r1;
        }
    }
}

// ---------------- launch ----------------
template<int CCH, int KS, int OC_N>
constexpr int conv_smem() {
    constexpr int SH = 32 + 2*(KS/2);
    return 2*CCH*SH*SH*4 + 2*CCH*KS*KS*OC_N*8;
}

extern "C" void kernel_launch(void* const* d_in, const int* in_sizes, int n_in,
                              void* d_out, int out_size)
{
    const float* f1      = (const float*)d_in[2];
    const float* f2      = (const float*)d_in[3];
    const float* flow_in = (const float*)d_in[4];
    const float* w_up    = (const float*)d_in[5];
    const float* w1 = (const float*)d_in[6];
    const float* b1 = (const float*)d_in[7];
    const float* w2 = (const float*)d_in[8];
    const float* b2 = (const float*)d_in[9];
    const float* w3 = (const float*)d_in[10];
    const float* b3 = (const float*)d_in[11];
    const float* w4 = (const float*)d_in[12];
    const float* b4 = (const float*)d_in[13];
    float* out = (float*)d_out;

    void *pcorr, *px1, *px2, *px3, *pwd;
    cudaGetSymbolAddress(&pcorr, g_corr);
    cudaGetSymbolAddress(&px1,   g_x1);
    cudaGetSymbolAddress(&px2,   g_x2);
    cudaGetSymbolAddress(&px3,   g_x3);
    cudaGetSymbolAddress(&pwd,   g_wdup);
    unsigned long long* wd = (unsigned long long*)pwd;

    constexpr int SM1 = conv_smem<7, 3, 8>();   // 72800 B
    constexpr int SM2 = conv_smem<4, 3, 8>();   // 41600 B
    constexpr int SM3 = conv_smem<4, 3, 8>();
    constexpr int SM4 = conv_smem<4, 5, 2>();   // 44672 B

    static bool attr_done = false;
    if (!attr_done) {
        cudaFuncSetAttribute(conv2d_k<49, 128, 3, 7, 8, 16, true,  false>,
                             cudaFuncAttributeMaxDynamicSharedMemorySize, SM1);
        cudaFuncSetAttribute(conv2d_k<128, 64, 3, 4, 8, 8, true,  false>,
                             cudaFuncAttributeMaxDynamicSharedMemorySize, SM2);
        cudaFuncSetAttribute(conv2d_k<64,  32, 3, 4, 8, 8, true,  false>,
                             cudaFuncAttributeMaxDynamicSharedMemorySize, SM3);
        cudaFuncSetAttribute(conv2d_k<32,   2, 5, 4, 2, 8, false, true >,
                             cudaFuncAttributeMaxDynamicSharedMemorySize, SM4);
        attr_done = true;
    }

    // 0) weight duplication (slabs per oc-block x chunk)
    dupw_k<<<(56448 + 255)/256, 256>>>(w1, wd + WD_OFF1, 56448, 49, 9, 7, 8, 7);
    dupw_k<<<(73728 + 255)/256, 256>>>(w2, wd + WD_OFF2, 73728, 128, 9, 4, 8, 32);
    dupw_k<<<(18432 + 255)/256, 256>>>(w3, wd + WD_OFF3, 18432, 64, 9, 4, 8, 16);
    dupw_k<<<(1600  + 255)/256, 256>>>(w4, wd + WD_OFF4, 1600, 32, 25, 4, 2, 8);

    // 1) upflow
    upflow_k<<<(BB*2*HW + 255)/256, 256>>>(flow_in, w_up);
    // 2) backwarp
    backwarp_k<<<(BB*HW + 255)/256, 256>>>(f2);
    // 3) correlation + leaky
    corr_k<<<dim3(WW/32, HH/8, BB), dim3(32, 8)>>>(f1);
    // 4) conv chain (conv1: 512-thread blocks for occupancy; others R9 shape)
    conv2d_k<49, 128, 3, 7, 8, 16, true,  false><<<dim3(6, 6, BB*16), dim3(32, 16), SM1>>>(
        (const float*)pcorr, wd + WD_OFF1, b1, (float*)px1);
    conv2d_k<128, 64, 3, 4, 8, 8, true,  false><<<dim3(6, 6, BB*8),  dim3(32, 8), SM2>>>(
        (const float*)px1,   wd + WD_OFF2, b2, (float*)px2);
    conv2d_k<64,  32, 3, 4, 8, 8, true,  false><<<dim3(6, 6, BB*4),  dim3(32, 8), SM3>>>(
        (const float*)px2,   wd + WD_OFF3, b3, (float*)px3);
    conv2d_k<32,   2, 5, 4, 2, 8, false, true ><<<dim3(6, 6, BB*1),  dim3(32, 8), SM4>>>(
        (const float*)px3,   wd + WD_OFF4, b4, out);
}

// round 15
// speedup vs baseline: 1.1701x; 1.1663x over previous
#include <cuda_runtime.h>
#include <cuda_bf16.h>
#include <cstdint>

// Problem constants
#define BB 4
#define CC_FEAT 96
#define HH 192
#define WW 192
#define HW (HH*WW)
#define MD 3
#define ND 49

// ---------------- scratch (device globals; no allocation allowed) ----------------
__device__ float g_flow [BB*2*HW];
__device__ float g_feat2[BB*CC_FEAT*HW];
__device__ float g_corr [BB*ND*HW];
__device__ float g_x1   [BB*128*HW];
__device__ float g_x2   [BB*64 *HW];
__device__ float g_x3   [BB*32 *HW];
// duplicated (w,w) weight pairs, slab layout per (oc_block, chunk)
__device__ unsigned long long g_wdup[160000];
#define WD_OFF1 0
#define WD_OFF2 56448      // 16*7*7*9*8
#define WD_OFF3 130176     // + 8*32*4*9*8
#define WD_OFF4 148608     // + 4*16*4*9*8
#define WD_END  150208     // + 1*8*4*25*2

// ---------------- f32x2 helpers ----------------
__device__ __forceinline__ unsigned long long pk2(float lo, float hi) {
    unsigned long long r;
    asm("mov.b64 %0, {%1, %2};" : "=l"(r) : "f"(lo), "f"(hi));
    return r;
}
__device__ __forceinline__ void upk2(unsigned long long v, float& lo, float& hi) {
    asm("mov.b64 {%0, %1}, %2;" : "=f"(lo), "=f"(hi) : "l"(v));
}
__device__ __forceinline__ void fma2(unsigned long long& d, unsigned long long a, unsigned long long b) {
    asm("fma.rn.f32x2 %0, %1, %2, %0;" : "+l"(d) : "l"(a), "l"(b));
}

// ---------------- cp.async helpers ----------------
__device__ __forceinline__ void cp4(unsigned int dst_smem, const void* src, unsigned int src_sz) {
    asm volatile("cp.async.ca.shared.global [%0], [%1], 4, %2;"
                 :: "r"(dst_smem), "l"(src), "r"(src_sz));
}
__device__ __forceinline__ void cp16(unsigned int dst_smem, const void* src) {
    asm volatile("cp.async.cg.shared.global [%0], [%1], 16;"
                 :: "r"(dst_smem), "l"(src));
}
__device__ __forceinline__ void cp_commit() {
    asm volatile("cp.async.commit_group;");
}
template<int N>
__device__ __forceinline__ void cp_wait() {
    asm volatile("cp.async.wait_group %0;" :: "n"(N));
}

// ---------------- 0) fused weight duplication (all 4 convs, 1 launch) -------------
__device__ __forceinline__ void dup_one(const float* __restrict__ w,
                                        unsigned long long* __restrict__ dst,
                                        int i, int CI, int KS2, int CCH,
                                        int OC_N, int NC)
{
    int oc = i % OC_N; int t = i / OC_N;
    int k  = t % KS2;  t /= KS2;
    int ci = t % CCH;  t /= CCH;
    int c  = t % NC;   int pb = t / NC;
    float wv = w[((pb*OC_N + oc)*CI + c*CCH + ci)*KS2 + k];
    unsigned int u = __float_as_uint(wv);
    dst[i] = (unsigned long long)u | ((unsigned long long)u << 32);
}

__global__ void __launch_bounds__(256) dupw_all_k(const float* __restrict__ w1,
                                                  const float* __restrict__ w2,
                                                  const float* __restrict__ w3,
                                                  const float* __restrict__ w4,
                                                  unsigned long long* __restrict__ wd)
{
    int i = blockIdx.x * 256 + threadIdx.x;
    if (i >= WD_END) return;
    if (i < WD_OFF2)      dup_one(w1, wd + WD_OFF1, i - WD_OFF1,  49,  9, 7, 8,  7);
    else if (i < WD_OFF3) dup_one(w2, wd + WD_OFF2, i - WD_OFF2, 128,  9, 4, 8, 32);
    else if (i < WD_OFF4) dup_one(w3, wd + WD_OFF3, i - WD_OFF3,  64,  9, 4, 8, 16);
    else                  dup_one(w4, wd + WD_OFF4, i - WD_OFF4,  32, 25, 4, 2,  8);
}

// ---------------- 1+2) fused upflow + backwarp ------------------------------------
// Each pixel computes its own 2 upflow values (same math/order as before), stores
// them to g_flow (needed later by conv4), then bilinearly warps 96 channels.
__global__ void __launch_bounds__(256) backwarp_fused_k(const float* __restrict__ feat,
                                                        const float* __restrict__ fl,
                                                        const float* __restrict__ w)
{
    int idx = blockIdx.x * 256 + threadIdx.x;
    if (idx >= BB*HW) return;
    int x = idx % WW;
    int y = (idx / WW) % HH;
    int b = idx / HW;

    // inline upflow for g = 0, 1
    float fv[2];
#pragma unroll
    for (int g = 0; g < 2; g++) {
        float acc = 0.f;
#pragma unroll
        for (int ky = 0; ky < 4; ky++) {
            int t = y + ky - 2;
            if (t & 1) continue;
            int iy = t >> 1;
            if (iy < 0 || iy >= 96) continue;
#pragma unroll
            for (int kx = 0; kx < 4; kx++) {
                int s = x + kx - 2;
                if (s & 1) continue;
                int ix = s >> 1;
                if (ix < 0 || ix >= 96) continue;
                acc += w[g*16 + (3-ky)*4 + (3-kx)] * fl[((b*2 + g)*96 + iy)*96 + ix];
            }
        }
        fv[g] = acc;
        g_flow[(b*2 + g)*HW + y*WW + x] = acc;
    }

    float fx = 2.5f * fv[0];
    float fy = 2.5f * fv[1];
    float gx = (float)x + fx;
    float gy = (float)y + fy;
    float x0f = floorf(gx), y0f = floorf(gy);
    float wx = gx - x0f, wy = gy - y0f;
    int x0 = (int)x0f, y0 = (int)y0f;
    int x1 = x0 + 1,  y1 = y0 + 1;

    float v00 = (x0 >= 0 && x0 < WW && y0 >= 0 && y0 < HH) ? 1.f : 0.f;
    float v01 = (x1 >= 0 && x1 < WW && y0 >= 0 && y0 < HH) ? 1.f : 0.f;
    float v10 = (x0 >= 0 && x0 < WW && y1 >= 0 && y1 < HH) ? 1.f : 0.f;
    float v11 = (x1 >= 0 && x1 < WW && y1 >= 0 && y1 < HH) ? 1.f : 0.f;

    int cx0 = min(max(x0, 0), WW-1), cx1 = min(max(x1, 0), WW-1);
    int cy0 = min(max(y0, 0), HH-1), cy1 = min(max(y1, 0), HH-1);

    float w00 = (1.f-wy)*(1.f-wx) * v00;
    float w01 = (1.f-wy)*wx       * v01;
    float w10 = wy*(1.f-wx)       * v10;
    float w11 = wy*wx             * v11;

    int o00 = cy0*WW + cx0, o01 = cy0*WW + cx1;
    int o10 = cy1*WW + cx0, o11 = cy1*WW + cx1;

    const float* fb = feat + (size_t)b*CC_FEAT*HW;
    float* ob = g_feat2 + (size_t)b*CC_FEAT*HW + y*WW + x;
#pragma unroll 4
    for (int c = 0; c < CC_FEAT; c++) {
        const float* p = fb + c*HW;
        ob[c*HW] = w00*p[o00] + w01*p[o01] + w10*p[o10] + w11*p[o11];
    }
}

// ---------------- 3) correlation + leaky, FMA2 x-pairs (proven in R5) -------------
// block (16,8)=128 threads; tile 32x8 pixels; each thread = 2 adjacent x pixels.
__global__ void __launch_bounds__(128) corr_k(const float* __restrict__ f1)
{
    __shared__ float s2[8][14][40];   // row width 40 floats for 8B-aligned LDS.64
    const int tx = threadIdx.x, ty = threadIdx.y;
    const int tid = ty*16 + tx;
    const int x0 = blockIdx.x * 32, y0 = blockIdx.y * 8;
    const int b = blockIdx.z;
    const int x = x0 + 2*tx, y = y0 + ty;

    unsigned long long acc[ND];
#pragma unroll
    for (int d = 0; d < ND; d++) acc[d] = 0ull;

    for (int cc0 = 0; cc0 < CC_FEAT; cc0 += 8) {
        for (int i = tid; i < 8*14*40; i += 128) {
            int ci  = i / (14*40);
            int rem = i - ci*(14*40);
            int r   = rem / 40;
            int cl  = rem - r*40;
            int gy = y0 + r - MD, gx = x0 + cl - MD;
            float v = 0.f;
            if (gy >= 0 && gy < HH && gx >= 0 && gx < WW)
                v = g_feat2[((b*CC_FEAT + cc0 + ci)*HH + gy)*WW + gx];
            s2[ci][r][cl] = v;
        }
        __syncthreads();

#pragma unroll 1
        for (int ci = 0; ci < 8; ci++) {
            const float2 fvv = *reinterpret_cast<const float2*>(
                &f1[((b*CC_FEAT + cc0 + ci)*HH + y)*WW + x]);
            unsigned long long fp = pk2(fvv.x, fvv.y);
#pragma unroll
            for (int dy = 0; dy < 7; dy++) {
                const float* rp = &s2[ci][ty + dy][2*tx];
                float2 L0 = *reinterpret_cast<const float2*>(rp);
                float2 L1 = *reinterpret_cast<const float2*>(rp + 2);
                float2 L2 = *reinterpret_cast<const float2*>(rp + 4);
                float2 L3 = *reinterpret_cast<const float2*>(rp + 6);
                float v[8] = {L0.x, L0.y, L1.x, L1.y, L2.x, L2.y, L3.x, L3.y};
#pragma unroll
                for (int dx = 0; dx < 7; dx++)
                    fma2(acc[dy*7 + dx], fp, pk2(v[dx], v[dx+1]));
            }
        }
        __syncthreads();
    }

#pragma unroll
    for (int d = 0; d < ND; d++) {
        float r0, r1;
        upk2(acc[d], r0, r1);
        r0 *= (1.f/96.f); r1 *= (1.f/96.f);
        r0 = (r0 >= 0.f) ? r0 : 0.1f * r0;
        r1 = (r1 >= 0.f) ? r1 : 0.1f * r1;
        *reinterpret_cast<float2*>(&g_corr[((b*ND + d)*HH + y)*WW + x]) =
            make_float2(r0, r1);
    }
}

// ---------------- 4) direct conv: row-pair FFMA2, pre-duplicated weights (R9) -----
// block (32,8)=256; tile 32x32. Thread: 1 x-pixel, rows (ty,ty+8) & (ty+16,ty+24)
// as 2 FFMA2 packs (pk2 of independent LDS -> free), OC_N chans.
// Per k-step: 4 LDS.32 + OC_N/2 LDS.128(broadcast) + 2*OC_N FFMA2.
template<int CI, int CO, int KS, int CCH, int OC_N, bool LEAKY, bool ADD_FLOW>
__global__ void __launch_bounds__(256) conv2d_k(const float* __restrict__ in,
                                                const unsigned long long* __restrict__ wdup,
                                                const float* __restrict__ bias,
                                                float* __restrict__ out)
{
    constexpr int PADK = KS / 2;
    constexpr int SH = 32 + 2*PADK;
    constexpr int SW = 32 + 2*PADK;
    constexpr int PLANE = SH*SW;
    constexpr int NC = CI / CCH;
    constexpr int IN_ELEMS = CCH*PLANE;
    constexpr int WU64 = CCH*KS*KS*OC_N;
    constexpr int NPOS = (PLANE + 255) / 256;

    extern __shared__ float dynsmem[];
    float* s_in = dynsmem;                                           // [2][IN_ELEMS]
    unsigned long long* s_w =
        reinterpret_cast<unsigned long long*>(dynsmem + 2*IN_ELEMS); // [2][WU64]

    const int tx = threadIdx.x, ty = threadIdx.y;
    const int tid = ty*32 + tx;
    const int x0 = blockIdx.x * 32, y0 = blockIdx.y * 32;
    constexpr int PER_B = CO / OC_N;
    const int b  = blockIdx.z / PER_B;
    const int pb = blockIdx.z % PER_B;
    const int ocb = pb * OC_N;

    int gofs[NPOS];
    unsigned int oksz[NPOS];
#pragma unroll
    for (int n = 0; n < NPOS; n++) {
        int i = tid + n*256;
        int r  = i / SW;
        int cl = i - r*SW;
        int gy = y0 + r - PADK, gx = x0 + cl - PADK;
        bool ok = (i < PLANE) && (gy >= 0) && (gy < HH) && (gx >= 0) && (gx < WW);
        gofs[n] = ok ? gy*WW + gx : 0;
        oksz[n] = ok ? 4u : 0u;
    }

    const unsigned long long* wslab = wdup + (size_t)pb*NC*WU64;

    unsigned long long acc[2][OC_N];
#pragma unroll
    for (int p = 0; p < 2; p++)
#pragma unroll
        for (int i = 0; i < OC_N; i++) acc[p][i] = 0ull;

    auto issue = [&](int c, int buf) {
        const float* inb = in + (size_t)(b*CI + c*CCH)*HW;
        unsigned int dbase = (unsigned int)__cvta_generic_to_shared(s_in + buf*IN_ELEMS);
#pragma unroll
        for (int ci = 0; ci < CCH; ci++) {
#pragma unroll
            for (int n = 0; n < NPOS; n++) {
                int i = tid + n*256;
                if (NPOS*256 != PLANE && i >= PLANE) break;
                cp4(dbase + (unsigned int)(ci*PLANE + i)*4u,
                    inb + ci*HW + gofs[n], oksz[n]);
            }
        }
        unsigned int wbase = (unsigned int)__cvta_generic_to_shared(s_w + buf*WU64);
        const unsigned long long* wsrc = wslab + (size_t)c*WU64;
#pragma unroll 1
        for (int i = tid; i < WU64/2; i += 256)
            cp16(wbase + (unsigned int)i*16u, wsrc + 2*i);
        cp_commit();
    };

    auto compute = [&](int buf) {
        const float* din = s_in + buf*IN_ELEMS;
        const unsigned long long* dw = s_w + buf*WU64;
#pragma unroll 1
        for (int ci = 0; ci < CCH; ci++) {
            const float* tb = din + ci*PLANE + ty*SW + tx;
#pragma unroll
            for (int ky = 0; ky < KS; ky++) {
#pragma unroll
                for (int kx = 0; kx < KS; kx++) {
                    float i0 = tb[(ky     )*SW + kx];
                    float i1 = tb[(ky +  8)*SW + kx];
                    float i2 = tb[(ky + 16)*SW + kx];
                    float i3 = tb[(ky + 24)*SW + kx];
                    unsigned long long P0 = pk2(i0, i1);
                    unsigned long long P1 = pk2(i2, i3);
                    const ulonglong2* wr = reinterpret_cast<const ulonglong2*>(
                        dw + (ci*KS*KS + ky*KS + kx)*OC_N);
#pragma unroll
                    for (int j = 0; j < OC_N/2; j++) {
                        ulonglong2 w2 = wr[j];
                        fma2(acc[0][2*j  ], P0, w2.x);
                        fma2(acc[0][2*j+1], P0, w2.y);
                        fma2(acc[1][2*j  ], P1, w2.x);
                        fma2(acc[1][2*j+1], P1, w2.y);
                    }
                }
            }
        }
    };

    issue(0, 0);
#pragma unroll 1
    for (int c = 0; c < NC; c++) {
        if (c + 1 < NC) { issue(c + 1, (c + 1) & 1); cp_wait<1>(); }
        else            { cp_wait<0>(); }
        __syncthreads();
        compute(c & 1);
        __syncthreads();
    }

    const int x = x0 + tx;
#pragma unroll
    for (int oc = 0; oc < OC_N; oc++) {
        float bv = bias[ocb + oc];
#pragma unroll
        for (int p = 0; p < 2; p++) {
            float r0, r1;
            upk2(acc[p][oc], r0, r1);
            int ya = y0 + ty + 16*p;
            int yb = ya + 8;
            r0 += bv; r1 += bv;
            if (LEAKY) {
                r0 = (r0 >= 0.f) ? r0 : 0.1f * r0;
                r1 = (r1 >= 0.f) ? r1 : 0.1f * r1;
            }
            if (ADD_FLOW) {
                r0 += g_flow[((b*2 + ocb + oc)*HH + ya)*WW + x];
                r1 += g_flow[((b*2 + ocb + oc)*HH + yb)*WW + x];
            }
            out[((b*CO + ocb + oc)*HH + ya)*WW + x] = r0;
            out[((b*CO + ocb + oc)*HH + yb)*WW + x] = r1;
        }
    }
}

// ---------------- launch ----------------
template<int CCH, int KS, int OC_N>
constexpr int conv_smem() {
    constexpr int SH = 32 + 2*(KS/2);
    return 2*CCH*SH*SH*4 + 2*CCH*KS*KS*OC_N*8;
}

extern "C" void kernel_launch(void* const* d_in, const int* in_sizes, int n_in,
                              void* d_out, int out_size)
{
    const float* f1      = (const float*)d_in[2];
    const float* f2      = (const float*)d_in[3];
    const float* flow_in = (const float*)d_in[4];
    const float* w_up    = (const float*)d_in[5];
    const float* w1 = (const float*)d_in[6];
    const float* b1 = (const float*)d_in[7];
    const float* w2 = (const float*)d_in[8];
    const float* b2 = (const float*)d_in[9];
    const float* w3 = (const float*)d_in[10];
    const float* b3 = (const float*)d_in[11];
    const float* w4 = (const float*)d_in[12];
    const float* b4 = (const float*)d_in[13];
    float* out = (float*)d_out;

    void *pcorr, *px1, *px2, *px3, *pwd;
    cudaGetSymbolAddress(&pcorr, g_corr);
    cudaGetSymbolAddress(&px1,   g_x1);
    cudaGetSymbolAddress(&px2,   g_x2);
    cudaGetSymbolAddress(&px3,   g_x3);
    cudaGetSymbolAddress(&pwd,   g_wdup);
    unsigned long long* wd = (unsigned long long*)pwd;

    constexpr int SM1 = conv_smem<7, 3, 8>();   // 72800 B
    constexpr int SM2 = conv_smem<4, 3, 8>();   // 41600 B
    constexpr int SM3 = conv_smem<4, 3, 8>();
    constexpr int SM4 = conv_smem<4, 5, 2>();   // 44672 B

    static bool attr_done = false;
    if (!attr_done) {
        cudaFuncSetAttribute(conv2d_k<49, 128, 3, 7, 8, true,  false>,
                             cudaFuncAttributeMaxDynamicSharedMemorySize, SM1);
        cudaFuncSetAttribute(conv2d_k<128, 64, 3, 4, 8, true,  false>,
                             cudaFuncAttributeMaxDynamicSharedMemorySize, SM2);
        cudaFuncSetAttribute(conv2d_k<64,  32, 3, 4, 8, true,  false>,
                             cudaFuncAttributeMaxDynamicSharedMemorySize, SM3);
        cudaFuncSetAttribute(conv2d_k<32,   2, 5, 4, 2, false, true >,
                             cudaFuncAttributeMaxDynamicSharedMemorySize, SM4);
        attr_done = true;
    }

    // (1) fused weight duplication — single launch
    dupw_all_k<<<(WD_END + 255)/256, 256>>>(w1, w2, w3, w4, wd);
    // (2) fused upflow + backwarp
    backwarp_fused_k<<<(BB*HW + 255)/256, 256>>>(f2, flow_in, w_up);
    // (3) correlation + leaky (x-pair FFMA2)
    corr_k<<<dim3(WW/32, HH/8, BB), dim3(16, 8)>>>(f1);
    // (4..7) conv chain — exact R9 configuration; conv1 is launch #4 (profiled slot)
    conv2d_k<49, 128, 3, 7, 8, true,  false><<<dim3(6, 6, BB*16), dim3(32, 8), SM1>>>(
        (const float*)pcorr, wd + WD_OFF1, b1, (float*)px1);
    conv2d_k<128, 64, 3, 4, 8, true,  false><<<dim3(6, 6, BB*8),  dim3(32, 8), SM2>>>(
        (const float*)px1,   wd + WD_OFF2, b2, (float*)px2);
    conv2d_k<64,  32, 3, 4, 8, true,  false><<<dim3(6, 6, BB*4),  dim3(32, 8), SM3>>>(
        (const float*)px2,   wd + WD_OFF3, b3, (float*)px3);
    conv2d_k<32,   2, 5, 4, 2, false, true ><<<dim3(6, 6, BB*1),  dim3(32, 8), SM4>>>(
        (const float*)px3,   wd + WD_OFF4, b4, out);
}

// round 16
// speedup vs baseline: 1.1710x; 1.0008x over previous
#include <cuda_runtime.h>
#include <cuda_bf16.h>
#include <cstdint>

// Problem constants
#define BB 4
#define CC_FEAT 96
#define HH 192
#define WW 192
#define HW (HH*WW)
#define MD 3
#define ND 49

// ---------------- scratch (device globals; no allocation allowed) ----------------
__device__ float g_flow [BB*2*HW];
__device__ float g_feat2[BB*CC_FEAT*HW];
__device__ float g_corr [BB*ND*HW];
__device__ float g_x1   [BB*128*HW];
__device__ float g_x2   [BB*64 *HW];
__device__ float g_x3   [BB*32 *HW];
// duplicated (w,w) weight pairs, slab layout per (oc_block, chunk)
__device__ unsigned long long g_wdup[160000];
#define WD_OFF1 0
#define WD_OFF2 56448      // 16*7*7*9*8
#define WD_OFF3 130176     // + 8*32*4*9*8
#define WD_OFF4 148608     // + 4*16*4*9*8
#define WD_END  150208     // + 1*8*4*25*2

// ---------------- f32x2 helpers ----------------
__device__ __forceinline__ unsigned long long pk2(float lo, float hi) {
    unsigned long long r;
    asm("mov.b64 %0, {%1, %2};" : "=l"(r) : "f"(lo), "f"(hi));
    return r;
}
__device__ __forceinline__ void upk2(unsigned long long v, float& lo, float& hi) {
    asm("mov.b64 {%0, %1}, %2;" : "=f"(lo), "=f"(hi) : "l"(v));
}
__device__ __forceinline__ void fma2(unsigned long long& d, unsigned long long a, unsigned long long b) {
    asm("fma.rn.f32x2 %0, %1, %2, %0;" : "+l"(d) : "l"(a), "l"(b));
}

// ---------------- cp.async helpers ----------------
__device__ __forceinline__ void cp4(unsigned int dst_smem, const void* src, unsigned int src_sz) {
    asm volatile("cp.async.ca.shared.global [%0], [%1], 4, %2;"
                 :: "r"(dst_smem), "l"(src), "r"(src_sz));
}
__device__ __forceinline__ void cp16(unsigned int dst_smem, const void* src) {
    asm volatile("cp.async.cg.shared.global [%0], [%1], 16;"
                 :: "r"(dst_smem), "l"(src));
}
__device__ __forceinline__ void cp_commit() {
    asm volatile("cp.async.commit_group;");
}
template<int N>
__device__ __forceinline__ void cp_wait() {
    asm volatile("cp.async.wait_group %0;" :: "n"(N));
}

// ---------------- 0) fused weight duplication (all 4 convs, 1 launch) -------------
__device__ __forceinline__ void dup_one(const float* __restrict__ w,
                                        unsigned long long* __restrict__ dst,
                                        int i, int CI, int KS2, int CCH,
                                        int OC_N, int NC)
{
    int oc = i % OC_N; int t = i / OC_N;
    int k  = t % KS2;  t /= KS2;
    int ci = t % CCH;  t /= CCH;
    int c  = t % NC;   int pb = t / NC;
    float wv = w[((pb*OC_N + oc)*CI + c*CCH + ci)*KS2 + k];
    unsigned int u = __float_as_uint(wv);
    dst[i] = (unsigned long long)u | ((unsigned long long)u << 32);
}

__global__ void __launch_bounds__(256) dupw_all_k(const float* __restrict__ w1,
                                                  const float* __restrict__ w2,
                                                  const float* __restrict__ w3,
                                                  const float* __restrict__ w4,
                                                  unsigned long long* __restrict__ wd)
{
    int i = blockIdx.x * 256 + threadIdx.x;
    if (i >= WD_END) return;
    if (i < WD_OFF2)      dup_one(w1, wd + WD_OFF1, i - WD_OFF1,  49,  9, 7, 8,  7);
    else if (i < WD_OFF3) dup_one(w2, wd + WD_OFF2, i - WD_OFF2, 128,  9, 4, 8, 32);
    else if (i < WD_OFF4) dup_one(w3, wd + WD_OFF3, i - WD_OFF3,  64,  9, 4, 8, 16);
    else                  dup_one(w4, wd + WD_OFF4, i - WD_OFF4,  32, 25, 4, 2,  8);
}

// ---------------- 1+2) fused upflow + backwarp ------------------------------------
// Each pixel computes its own 2 upflow values (same math/order as before), stores
// them to g_flow (needed later by conv4), then bilinearly warps 96 channels.
__global__ void __launch_bounds__(256) backwarp_fused_k(const float* __restrict__ feat,
                                                        const float* __restrict__ fl,
                                                        const float* __restrict__ w)
{
    int idx = blockIdx.x * 256 + threadIdx.x;
    if (idx >= BB*HW) return;
    int x = idx % WW;
    int y = (idx / WW) % HH;
    int b = idx / HW;

    // inline upflow for g = 0, 1
    float fv[2];
#pragma unroll
    for (int g = 0; g < 2; g++) {
        float acc = 0.f;
#pragma unroll
        for (int ky = 0; ky < 4; ky++) {
            int t = y + ky - 2;
            if (t & 1) continue;
            int iy = t >> 1;
            if (iy < 0 || iy >= 96) continue;
#pragma unroll
            for (int kx = 0; kx < 4; kx++) {
                int s = x + kx - 2;
                if (s & 1) continue;
                int ix = s >> 1;
                if (ix < 0 || ix >= 96) continue;
                acc += w[g*16 + (3-ky)*4 + (3-kx)] * fl[((b*2 + g)*96 + iy)*96 + ix];
            }
        }
        fv[g] = acc;
        g_flow[(b*2 + g)*HW + y*WW + x] = acc;
    }

    float fx = 2.5f * fv[0];
    float fy = 2.5f * fv[1];
    float gx = (float)x + fx;
    float gy = (float)y + fy;
    float x0f = floorf(gx), y0f = floorf(gy);
    float wx = gx - x0f, wy = gy - y0f;
    int x0 = (int)x0f, y0 = (int)y0f;
    int x1 = x0 + 1,  y1 = y0 + 1;

    float v00 = (x0 >= 0 && x0 < WW && y0 >= 0 && y0 < HH) ? 1.f : 0.f;
    float v01 = (x1 >= 0 && x1 < WW && y0 >= 0 && y0 < HH) ? 1.f : 0.f;
    float v10 = (x0 >= 0 && x0 < WW && y1 >= 0 && y1 < HH) ? 1.f : 0.f;
    float v11 = (x1 >= 0 && x1 < WW && y1 >= 0 && y1 < HH) ? 1.f : 0.f;

    int cx0 = min(max(x0, 0), WW-1), cx1 = min(max(x1, 0), WW-1);
    int cy0 = min(max(y0, 0), HH-1), cy1 = min(max(y1, 0), HH-1);

    float w00 = (1.f-wy)*(1.f-wx) * v00;
    float w01 = (1.f-wy)*wx       * v01;
    float w10 = wy*(1.f-wx)       * v10;
    float w11 = wy*wx             * v11;

    int o00 = cy0*WW + cx0, o01 = cy0*WW + cx1;
    int o10 = cy1*WW + cx0, o11 = cy1*WW + cx1;

    const float* fb = feat + (size_t)b*CC_FEAT*HW;
    float* ob = g_feat2 + (size_t)b*CC_FEAT*HW + y*WW + x;
#pragma unroll 4
    for (int c = 0; c < CC_FEAT; c++) {
        const float* p = fb + c*HW;
        ob[c*HW] = w00*p[o00] + w01*p[o01] + w10*p[o10] + w11*p[o11];
    }
}

// ---------------- 3) correlation + leaky, FMA2 x-pairs (proven in R5) -------------
// block (16,8)=128 threads; tile 32x8 pixels; each thread = 2 adjacent x pixels.
__global__ void __launch_bounds__(128) corr_k(const float* __restrict__ f1)
{
    __shared__ float s2[8][14][40];   // row width 40 floats for 8B-aligned LDS.64
    const int tx = threadIdx.x, ty = threadIdx.y;
    const int tid = ty*16 + tx;
    const int x0 = blockIdx.x * 32, y0 = blockIdx.y * 8;
    const int b = blockIdx.z;
    const int x = x0 + 2*tx, y = y0 + ty;

    unsigned long long acc[ND];
#pragma unroll
    for (int d = 0; d < ND; d++) acc[d] = 0ull;

    for (int cc0 = 0; cc0 < CC_FEAT; cc0 += 8) {
        for (int i = tid; i < 8*14*40; i += 128) {
            int ci  = i / (14*40);
            int rem = i - ci*(14*40);
            int r   = rem / 40;
            int cl  = rem - r*40;
            int gy = y0 + r - MD, gx = x0 + cl - MD;
            float v = 0.f;
            if (gy >= 0 && gy < HH && gx >= 0 && gx < WW)
                v = g_feat2[((b*CC_FEAT + cc0 + ci)*HH + gy)*WW + gx];
            s2[ci][r][cl] = v;
        }
        __syncthreads();

#pragma unroll 1
        for (int ci = 0; ci < 8; ci++) {
            const float2 fvv = *reinterpret_cast<const float2*>(
                &f1[((b*CC_FEAT + cc0 + ci)*HH + y)*WW + x]);
            unsigned long long fp = pk2(fvv.x, fvv.y);
#pragma unroll
            for (int dy = 0; dy < 7; dy++) {
                const float* rp = &s2[ci][ty + dy][2*tx];
                float2 L0 = *reinterpret_cast<const float2*>(rp);
                float2 L1 = *reinterpret_cast<const float2*>(rp + 2);
                float2 L2 = *reinterpret_cast<const float2*>(rp + 4);
                float2 L3 = *reinterpret_cast<const float2*>(rp + 6);
                float v[8] = {L0.x, L0.y, L1.x, L1.y, L2.x, L2.y, L3.x, L3.y};
#pragma unroll
                for (int dx = 0; dx < 7; dx++)
                    fma2(acc[dy*7 + dx], fp, pk2(v[dx], v[dx+1]));
            }
        }
        __syncthreads();
    }

#pragma unroll
    for (int d = 0; d < ND; d++) {
        float r0, r1;
        upk2(acc[d], r0, r1);
        r0 *= (1.f/96.f); r1 *= (1.f/96.f);
        r0 = (r0 >= 0.f) ? r0 : 0.1f * r0;
        r1 = (r1 >= 0.f) ? r1 : 0.1f * r1;
        *reinterpret_cast<float2*>(&g_corr[((b*ND + d)*HH + y)*WW + x]) =
            make_float2(r0, r1);
    }
}

// ---------------- 4) direct conv: row-pair FFMA2, pre-duplicated weights (R9) -----
// block (32,8)=256; tile 32x32. Thread: 1 x-pixel, rows (ty,ty+8) & (ty+16,ty+24)
// as 2 FFMA2 packs (pk2 of independent LDS -> free), OC_N chans.
// Per k-step: 4 LDS.32 + OC_N/2 LDS.128(broadcast) + 2*OC_N FFMA2.
template<int CI, int CO, int KS, int CCH, int OC_N, bool LEAKY, bool ADD_FLOW>
__global__ void __launch_bounds__(256) conv2d_k(const float* __restrict__ in,
                                                const unsigned long long* __restrict__ wdup,
                                                const float* __restrict__ bias,
                                                float* __restrict__ out)
{
    constexpr int PADK = KS / 2;
    constexpr int SH = 32 + 2*PADK;
    constexpr int SW = 32 + 2*PADK;
    constexpr int PLANE = SH*SW;
    constexpr int NC = CI / CCH;
    constexpr int IN_ELEMS = CCH*PLANE;
    constexpr int WU64 = CCH*KS*KS*OC_N;
    constexpr int NPOS = (PLANE + 255) / 256;

    extern __shared__ float dynsmem[];
    float* s_in = dynsmem;                                           // [2][IN_ELEMS]
    unsigned long long* s_w =
        reinterpret_cast<unsigned long long*>(dynsmem + 2*IN_ELEMS); // [2][WU64]

    const int tx = threadIdx.x, ty = threadIdx.y;
    const int tid = ty*32 + tx;
    const int x0 = blockIdx.x * 32, y0 = blockIdx.y * 32;
    constexpr int PER_B = CO / OC_N;
    const int b  = blockIdx.z / PER_B;
    const int pb = blockIdx.z % PER_B;
    const int ocb = pb * OC_N;

    int gofs[NPOS];
    unsigned int oksz[NPOS];
#pragma unroll
    for (int n = 0; n < NPOS; n++) {
        int i = tid + n*256;
        int r  = i / SW;
        int cl = i - r*SW;
        int gy = y0 + r - PADK, gx = x0 + cl - PADK;
        bool ok = (i < PLANE) && (gy >= 0) && (gy < HH) && (gx >= 0) && (gx < WW);
        gofs[n] = ok ? gy*WW + gx : 0;
        oksz[n] = ok ? 4u : 0u;
    }

    const unsigned long long* wslab = wdup + (size_t)pb*NC*WU64;

    unsigned long long acc[2][OC_N];
#pragma unroll
    for (int p = 0; p < 2; p++)
#pragma unroll
        for (int i = 0; i < OC_N; i++) acc[p][i] = 0ull;

    auto issue = [&](int c, int buf) {
        const float* inb = in + (size_t)(b*CI + c*CCH)*HW;
        unsigned int dbase = (unsigned int)__cvta_generic_to_shared(s_in + buf*IN_ELEMS);
#pragma unroll
        for (int ci = 0; ci < CCH; ci++) {
#pragma unroll
            for (int n = 0; n < NPOS; n++) {
                int i = tid + n*256;
                if (NPOS*256 != PLANE && i >= PLANE) break;
                cp4(dbase + (unsigned int)(ci*PLANE + i)*4u,
                    inb + ci*HW + gofs[n], oksz[n]);
            }
        }
        unsigned int wbase = (unsigned int)__cvta_generic_to_shared(s_w + buf*WU64);
        const unsigned long long* wsrc = wslab + (size_t)c*WU64;
#pragma unroll 1
        for (int i = tid; i < WU64/2; i += 256)
            cp16(wbase + (unsigned int)i*16u, wsrc + 2*i);
        cp_commit();
    };

    auto compute = [&](int buf) {
        const float* din = s_in + buf*IN_ELEMS;
        const unsigned long long* dw = s_w + buf*WU64;
#pragma unroll 1
        for (int ci = 0; ci < CCH; ci++) {
            const float* tb = din + ci*PLANE + ty*SW + tx;
#pragma unroll
            for (int ky = 0; ky < KS; ky++) {
#pragma unroll
                for (int kx = 0; kx < KS; kx++) {
                    float i0 = tb[(ky     )*SW + kx];
                    float i1 = tb[(ky +  8)*SW + kx];
                    float i2 = tb[(ky + 16)*SW + kx];
                    float i3 = tb[(ky + 24)*SW + kx];
                    unsigned long long P0 = pk2(i0, i1);
                    unsigned long long P1 = pk2(i2, i3);
                    const ulonglong2* wr = reinterpret_cast<const ulonglong2*>(
                        dw + (ci*KS*KS + ky*KS + kx)*OC_N);
#pragma unroll
                    for (int j = 0; j < OC_N/2; j++) {
                        ulonglong2 w2 = wr[j];
                        fma2(acc[0][2*j  ], P0, w2.x);
                        fma2(acc[0][2*j+1], P0, w2.y);
                        fma2(acc[1][2*j  ], P1, w2.x);
                        fma2(acc[1][2*j+1], P1, w2.y);
                    }
                }
            }
        }
    };

    issue(0, 0);
#pragma unroll 1
    for (int c = 0; c < NC; c++) {
        if (c + 1 < NC) { issue(c + 1, (c + 1) & 1); cp_wait<1>(); }
        else            { cp_wait<0>(); }
        __syncthreads();
        compute(c & 1);
        __syncthreads();
    }

    const int x = x0 + tx;
#pragma unroll
    for (int oc = 0; oc < OC_N; oc++) {
        float bv = bias[ocb + oc];
#pragma unroll
        for (int p = 0; p < 2; p++) {
            float r0, r1;
            upk2(acc[p][oc], r0, r1);
            int ya = y0 + ty + 16*p;
            int yb = ya + 8;
            r0 += bv; r1 += bv;
            if (LEAKY) {
                r0 = (r0 >= 0.f) ? r0 : 0.1f * r0;
                r1 = (r1 >= 0.f) ? r1 : 0.1f * r1;
            }
            if (ADD_FLOW) {
                r0 += g_flow[((b*2 + ocb + oc)*HH + ya)*WW + x];
                r1 += g_flow[((b*2 + ocb + oc)*HH + yb)*WW + x];
            }
            out[((b*CO + ocb + oc)*HH + ya)*WW + x] = r0;
            out[((b*CO + ocb + oc)*HH + yb)*WW + x] = r1;
        }
    }
}

// ---------------- launch ----------------
template<int CCH, int KS, int OC_N>
constexpr int conv_smem() {
    constexpr int SH = 32 + 2*(KS/2);
    return 2*CCH*SH*SH*4 + 2*CCH*KS*KS*OC_N*8;
}

extern "C" void kernel_launch(void* const* d_in, const int* in_sizes, int n_in,
                              void* d_out, int out_size)
{
    const float* f1      = (const float*)d_in[2];
    const float* f2      = (const float*)d_in[3];
    const float* flow_in = (const float*)d_in[4];
    const float* w_up    = (const float*)d_in[5];
    const float* w1 = (const float*)d_in[6];
    const float* b1 = (const float*)d_in[7];
    const float* w2 = (const float*)d_in[8];
    const float* b2 = (const float*)d_in[9];
    const float* w3 = (const float*)d_in[10];
    const float* b3 = (const float*)d_in[11];
    const float* w4 = (const float*)d_in[12];
    const float* b4 = (const float*)d_in[13];
    float* out = (float*)d_out;

    void *pcorr, *px1, *px2, *px3, *pwd;
    cudaGetSymbolAddress(&pcorr, g_corr);
    cudaGetSymbolAddress(&px1,   g_x1);
    cudaGetSymbolAddress(&px2,   g_x2);
    cudaGetSymbolAddress(&px3,   g_x3);
    cudaGetSymbolAddress(&pwd,   g_wdup);
    unsigned long long* wd = (unsigned long long*)pwd;

    constexpr int SM1 = conv_smem<7, 3, 8>();   // 72800 B
    constexpr int SM2 = conv_smem<4, 3, 8>();   // 41600 B
    constexpr int SM3 = conv_smem<4, 3, 8>();
    constexpr int SM4 = conv_smem<4, 5, 2>();   // 44672 B

    static bool attr_done = false;
    if (!attr_done) {
        cudaFuncSetAttribute(conv2d_k<49, 128, 3, 7, 8, true,  false>,
                             cudaFuncAttributeMaxDynamicSharedMemorySize, SM1);
        cudaFuncSetAttribute(conv2d_k<128, 64, 3, 4, 8, true,  false>,
                             cudaFuncAttributeMaxDynamicSharedMemorySize, SM2);
        cudaFuncSetAttribute(conv2d_k<64,  32, 3, 4, 8, true,  false>,
                             cudaFuncAttributeMaxDynamicSharedMemorySize, SM3);
        cudaFuncSetAttribute(conv2d_k<32,   2, 5, 4, 2, false, true >,
                             cudaFuncAttributeMaxDynamicSharedMemorySize, SM4);
        attr_done = true;
    }

    // (1) fused weight duplication — single launch
    dupw_all_k<<<(WD_END + 255)/256, 256>>>(w1, w2, w3, w4, wd);
    // (2) fused upflow + backwarp
    backwarp_fused_k<<<(BB*HW + 255)/256, 256>>>(f2, flow_in, w_up);
    // (3) correlation + leaky (x-pair FFMA2)
    corr_k<<<dim3(WW/32, HH/8, BB), dim3(16, 8)>>>(f1);
    // (4..7) conv chain — exact R9 configuration; conv1 is launch #4 (profiled slot)
    conv2d_k<49, 128, 3, 7, 8, true,  false><<<dim3(6, 6, BB*16), dim3(32, 8), SM1>>>(
        (const float*)pcorr, wd + WD_OFF1, b1, (float*)px1);
    conv2d_k<128, 64, 3, 4, 8, true,  false><<<dim3(6, 6, BB*8),  dim3(32, 8), SM2>>>(
        (const float*)px1,   wd + WD_OFF2, b2, (float*)px2);
    conv2d_k<64,  32, 3, 4, 8, true,  false><<<dim3(6, 6, BB*4),  dim3(32, 8), SM3>>>(
        (const float*)px2,   wd + WD_OFF3, b3, (float*)px3);
    conv2d_k<32,   2, 5, 4, 2, false, true ><<<dim3(6, 6, BB*1),  dim3(32, 8), SM4>>>(
        (const float*)px3,   wd + WD_OFF4, b4, out);
}